// round 10
// baseline (speedup 1.0000x reference)
#include <cuda_runtime.h>
#include <cstdint>

// YoloLayer: x (64, 30, 152, 152) f32 -> out (64, 3*152*152, 10) f32
// Persistent grid-stride version of the best variant (R8):
// VEC=2 LDG.64 streaming loads, 20KB block smem staging, STG.128 streaming
// stores. grid = SMs * blocks/SM; each block loops over tiles.

#define G     152
#define GG    (G * G)            // 23104, even
#define A     3
#define F     10
#define B     64
#define BLK   256
#define VEC   2
#define POS_PER_BLK (BLK * VEC)  // 512
#define NTILES (B * A * GG / POS_PER_BLK)   // 8664

__constant__ float c_anchor_w[A] = {12.0f, 19.0f, 40.0f};
__constant__ float c_anchor_h[A] = {16.0f, 36.0f, 28.0f};

__device__ __forceinline__ float fsigmoid(float v) {
    return 1.0f / (1.0f + __expf(-v));
}

__global__ __launch_bounds__(BLK) void yolo_kernel(
    const float* __restrict__ x,
    const int*   __restrict__ img,
    float*       __restrict__ out,
    int nblocks)
{
    __shared__ __align__(16) float s[POS_PER_BLK * F];   // 20480 B

    const int tid = threadIdx.x;

    int iv = img[0];
    float img_f = (iv > 0 && iv < 1000000) ? (float)iv : __int_as_float(iv);
    const float stride = img_f / (float)G;               // 8.0

    const float SXY = 1.05f;
    const float OFF = 0.025f;

    for (int tile = blockIdx.x; tile < NTILES; tile += nblocks) {
        const int p0 = (tile * BLK + tid) * VEC;         // even position

        // Both positions share b, a, yy (G even, GG even)
        const int b    = p0 / (A * GG);
        int rem        = p0 - b * (A * GG);
        const int a    = rem / GG;
        const int sidx = rem - a * GG;
        const int yy   = sidx / G;
        const int xx0  = sidx - yy * G;

        const float* base = x + ((size_t)(b * (A * F) + a * F)) * GG + sidx;

        // 10 independent streaming LDG.64 (read-once, evict-first)
        float2 v[F];
#pragma unroll
        for (int f = 0; f < F; f++)
            v[f] = __ldcs((const float2*)(base + (size_t)f * GG));

        const float aw = c_anchor_w[a];
        const float ah = c_anchor_h[a];
        const float fy = (float)yy;

        float* sp = s + tid * (VEC * F);
#pragma unroll
        for (int j = 0; j < VEC; j++) {
            float r0 = (fsigmoid(j ? v[0].y : v[0].x) * SXY - OFF + (float)(xx0 + j)) * stride;
            float r1 = (fsigmoid(j ? v[1].y : v[1].x) * SXY - OFF + fy) * stride;
            float r2 = __expf(j ? v[2].y : v[2].x) * aw;
            float r3 = __expf(j ? v[3].y : v[3].x) * ah;
            ((float4*)(sp + j * F))[0] = make_float4(r0, r1, r2, r3);
            float r4 = j ? v[4].y : v[4].x;
            float r5 = j ? v[5].y : v[5].x;
            float r6 = fsigmoid(j ? v[6].y : v[6].x);
            float r7 = fsigmoid(j ? v[7].y : v[7].x);
            ((float4*)(sp + j * F))[1] = make_float4(r4, r5, r6, r7);
            float r8 = fsigmoid(j ? v[8].y : v[8].x);
            float r9 = fsigmoid(j ? v[9].y : v[9].x);
            ((float2*)(sp + j * F))[4] = make_float2(r8, r9);
        }

        __syncthreads();

        // Tile output slice: 5120 contiguous floats = 1280 float4.
        // 5 fully-coalesced streaming STG.128 per thread.
        float4* ob = (float4*)(out + (size_t)tile * (POS_PER_BLK * F));
        const float4* sf = (const float4*)s;
#pragma unroll
        for (int jj = 0; jj < 5; jj++)
            __stcs(&ob[tid + jj * BLK], sf[tid + jj * BLK]);

        __syncthreads();   // protect smem before next tile overwrites it
    }
}

extern "C" void kernel_launch(void* const* d_in, const int* in_sizes, int n_in,
                              void* d_out, int out_size)
{
    const float* x   = (const float*)d_in[0];
    const int*   img = (n_in >= 2) ? (const int*)d_in[1] : nullptr;
    float*       out = (float*)d_out;

    // Persistent-ish: enough blocks to fill every SM at measured residency.
    const int nblocks = 148 * 6;   // 888
    yolo_kernel<<<nblocks, BLK>>>(x, img, out, nblocks);
}

// round 11
// speedup vs baseline: 1.1517x; 1.1517x over previous
#include <cuda_runtime.h>
#include <cstdint>

// YoloLayer: x (64, 30, 152, 152) f32 -> out (64, 3*152*152, 10) f32
// R8 structure at BLK=128: VEC=2 streaming LDG.64, smem transpose (5KB/tile... 
// 10KB per block), streaming STG.128. 4-warp barrier scope, 12 blocks/SM.

#define G     152
#define GG    (G * G)            // 23104, even
#define A     3
#define F     10
#define B     64
#define BLK   128
#define VEC   2
#define POS_PER_BLK (BLK * VEC)  // 256

__constant__ float c_anchor_w[A] = {12.0f, 19.0f, 40.0f};
__constant__ float c_anchor_h[A] = {16.0f, 36.0f, 28.0f};

__device__ __forceinline__ float fsigmoid(float v) {
    return 1.0f / (1.0f + __expf(-v));
}

__global__ __launch_bounds__(BLK) void yolo_kernel(
    const float* __restrict__ x,
    const int*   __restrict__ img,
    float*       __restrict__ out)
{
    __shared__ __align__(16) float s[POS_PER_BLK * F];   // 10240 B

    const int tid = threadIdx.x;
    const int p0  = (blockIdx.x * BLK + tid) * VEC;      // even position

    int iv = img[0];
    float img_f = (iv > 0 && iv < 1000000) ? (float)iv : __int_as_float(iv);
    const float stride = img_f / (float)G;               // 8.0

    // Both positions share b, a, yy (G even, GG even)
    const int b    = p0 / (A * GG);
    int rem        = p0 - b * (A * GG);
    const int a    = rem / GG;
    const int sidx = rem - a * GG;
    const int yy   = sidx / G;
    const int xx0  = sidx - yy * G;

    const float* base = x + ((size_t)(b * (A * F) + a * F)) * GG + sidx;

    // 10 independent streaming LDG.64 (read-once, evict-first)
    float2 v[F];
#pragma unroll
    for (int f = 0; f < F; f++)
        v[f] = __ldcs((const float2*)(base + (size_t)f * GG));

    const float SXY = 1.05f;
    const float OFF = 0.025f;
    const float aw  = c_anchor_w[a];
    const float ah  = c_anchor_h[a];
    const float fy  = (float)yy;

    float* sp = s + tid * (VEC * F);
#pragma unroll
    for (int j = 0; j < VEC; j++) {
        float r0 = (fsigmoid(j ? v[0].y : v[0].x) * SXY - OFF + (float)(xx0 + j)) * stride;
        float r1 = (fsigmoid(j ? v[1].y : v[1].x) * SXY - OFF + fy) * stride;
        float r2 = __expf(j ? v[2].y : v[2].x) * aw;
        float r3 = __expf(j ? v[3].y : v[3].x) * ah;
        ((float4*)(sp + j * F))[0] = make_float4(r0, r1, r2, r3);
        float r4 = j ? v[4].y : v[4].x;
        float r5 = j ? v[5].y : v[5].x;
        float r6 = fsigmoid(j ? v[6].y : v[6].x);
        float r7 = fsigmoid(j ? v[7].y : v[7].x);
        ((float4*)(sp + j * F))[1] = make_float4(r4, r5, r6, r7);
        float r8 = fsigmoid(j ? v[8].y : v[8].x);
        float r9 = fsigmoid(j ? v[9].y : v[9].x);
        ((float2*)(sp + j * F))[4] = make_float2(r8, r9);
    }

    __syncthreads();   // 4-warp barrier

    // Block output slice: 256*10 = 2560 contiguous floats = 640 float4.
    // 5 fully-coalesced streaming STG.128 per thread.
    float4* ob = (float4*)(out + (size_t)blockIdx.x * (POS_PER_BLK * F));
    const float4* sf = (const float4*)s;
#pragma unroll
    for (int jj = 0; jj < 5; jj++)
        __stcs(&ob[tid + jj * BLK], sf[tid + jj * BLK]);
}

extern "C" void kernel_launch(void* const* d_in, const int* in_sizes, int n_in,
                              void* d_out, int out_size)
{
    const float* x   = (const float*)d_in[0];
    const int*   img = (n_in >= 2) ? (const int*)d_in[1] : nullptr;
    float*       out = (float*)d_out;

    const int total = B * A * GG;             // 4,435,968
    const int grid  = total / POS_PER_BLK;    // 17328 exactly

    yolo_kernel<<<grid, BLK>>>(x, img, out);
}